// round 1
// baseline (speedup 1.0000x reference)
#include <cuda_runtime.h>
#include <cuda_bf16.h>
#include <cstdint>

#define N_NODES 50000
#define N_EDGES 800000
#define HID 64
#define HEADS 4
#define CDIM 64
#define HC 256   // HEADS*CDIM
#define L_LAYERS 2
#define NEG_SLOPE 0.2f
#define LN_EPS 1e-5f

// ---------------- device scratch (no allocations allowed) ----------------
__device__ float g_x[(size_t)N_NODES * HC];       // projected nodes [N,256]
__device__ float g_acc[(size_t)N_NODES * HC];     // message accumulator [N,256]
__device__ float g_as[N_NODES * HEADS];           // alpha_src [N,4]
__device__ float g_ad[N_NODES * HEADS];           // alpha_dst [N,4]
__device__ float g_denom[N_NODES * HEADS];        // softmax denom [N,4]
__device__ float g_ex[(size_t)N_EDGES * HEADS];   // exp(alpha) per edge [E,4]
__device__ float g_z[(size_t)N_NODES * HID];      // inter-layer activations
__device__ int   g_src[N_EDGES];
__device__ int   g_dst[N_EDGES];
__device__ float g_M[12];                         // edge-attr dual matrix [3][4]
__device__ int   g_is64;

// ---------------- helpers ----------------
__device__ __forceinline__ void red_add_v4(float* addr, float4 v) {
    asm volatile("red.global.add.v4.f32 [%0], {%1,%2,%3,%4};"
                 :: "l"(addr), "f"(v.x), "f"(v.y), "f"(v.z), "f"(v.w) : "memory");
}

// ---------------- K0a: detect edge_index dtype ----------------
__global__ void k_detect(const int* __restrict__ ei32) {
    int zeros = 0;
    for (int i = 1; i < 256; i += 2) if (ei32[i] == 0) zeros++;
    g_is64 = (zeros > 100) ? 1 : 0;   // int64 data: high words all zero
}

// ---------------- K0b: normalize edge index to int32 src/dst ----------------
__global__ void k_convert(const void* __restrict__ ei) {
    int e = blockIdx.x * blockDim.x + threadIdx.x;
    if (e >= N_EDGES) return;
    if (g_is64) {
        const long long* p = (const long long*)ei;
        g_src[e] = (int)p[e];
        g_dst[e] = (int)p[N_EDGES + e];
    } else {
        const int* p = (const int*)ei;
        g_src[e] = p[e];
        g_dst[e] = p[N_EDGES + e];
    }
}

// ---------------- K0c: zero accumulators ----------------
__global__ void k_zero() {
    const float4 z = make_float4(0.f, 0.f, 0.f, 0.f);
    size_t i = (size_t)blockIdx.x * blockDim.x + threadIdx.x;
    size_t stride = (size_t)gridDim.x * blockDim.x;
    const size_t n_acc4 = (size_t)N_NODES * HC / 4;
    for (size_t j = i; j < n_acc4; j += stride) ((float4*)g_acc)[j] = z;
    const size_t n_dn4 = (size_t)N_NODES * HEADS / 4;
    for (size_t j = i; j < n_dn4; j += stride) ((float4*)g_denom)[j] = z;
}

// ---------------- K0d: M[d][h] = sum_c We[d, h*64+c] * a_e[h, c] ----------------
__global__ void k_M(const float* __restrict__ We, const float* __restrict__ a_e) {
    int t = threadIdx.x;
    if (t < 12) {
        int d = t >> 2, h = t & 3;
        float s = 0.f;
        for (int c = 0; c < CDIM; c++)
            s += We[d * HC + h * CDIM + c] * a_e[h * CDIM + c];
        g_M[t] = s;   // layout g_M[d*4+h]
    }
}

// ---------------- K1: node projection + alpha_src/alpha_dst ----------------
// x[n,j] = sum_k z[n,k] * W[k,j];  alpha_s[n,h] = sum_c x[n,h,c]*a_s[h,c]
// 256 threads, 8 nodes per iteration, W cached in shared.
#define NB 8
__global__ void __launch_bounds__(256) k_node_proj(
    const float* __restrict__ z, const float* __restrict__ W,
    const float* __restrict__ a_s, const float* __restrict__ a_d)
{
    extern __shared__ float smem[];
    float* Wsh  = smem;                 // 64*256 = 16384 floats
    float* zshT = smem + 16384;         // [k][nb] transposed, 512 floats
    float* reds = smem + 16896;         // [nb][warp] 64 floats
    float* redd = smem + 16960;         // 64 floats

    const int tid = threadIdx.x;
    for (int i = tid; i < (HID * HC) / 4; i += 256)
        ((float4*)Wsh)[i] = ((const float4*)W)[i];
    const float as = a_s[tid];
    const float ad = a_d[tid];
    __syncthreads();

    const int lane = tid & 31;
    const int wid = tid >> 5;

    for (int g = blockIdx.x; g * NB < N_NODES; g += gridDim.x) {
        const int n0 = g * NB;
        // load 8 z-rows transposed: zshT[k*8+nb] = z[(n0+nb)*64+k]
        for (int i = tid; i < NB * HID; i += 256) {
            int nb = i >> 6, k = i & 63;
            zshT[k * NB + nb] = z[(size_t)n0 * HID + i];
        }
        __syncthreads();

        float acc[NB];
#pragma unroll
        for (int nb = 0; nb < NB; nb++) acc[nb] = 0.f;

#pragma unroll
        for (int k = 0; k < HID; k++) {
            float w = Wsh[k * HC + tid];
            float4 za = ((float4*)zshT)[k * 2];
            float4 zb = ((float4*)zshT)[k * 2 + 1];
            acc[0] = fmaf(za.x, w, acc[0]);
            acc[1] = fmaf(za.y, w, acc[1]);
            acc[2] = fmaf(za.z, w, acc[2]);
            acc[3] = fmaf(za.w, w, acc[3]);
            acc[4] = fmaf(zb.x, w, acc[4]);
            acc[5] = fmaf(zb.y, w, acc[5]);
            acc[6] = fmaf(zb.z, w, acc[6]);
            acc[7] = fmaf(zb.w, w, acc[7]);
        }

#pragma unroll
        for (int nb = 0; nb < NB; nb++)
            g_x[(size_t)(n0 + nb) * HC + tid] = acc[nb];

        // per-head reductions (head h = tid>>6, warps 2h and 2h+1)
#pragma unroll
        for (int nb = 0; nb < NB; nb++) {
            float ps = acc[nb] * as;
            float pd = acc[nb] * ad;
#pragma unroll
            for (int o = 16; o; o >>= 1) {
                ps += __shfl_down_sync(0xffffffffu, ps, o);
                pd += __shfl_down_sync(0xffffffffu, pd, o);
            }
            if (lane == 0) { reds[nb * 8 + wid] = ps; redd[nb * 8 + wid] = pd; }
        }
        __syncthreads();
        if (tid < 32) {
            int nb = tid >> 2, h = tid & 3;
            g_as[(n0 + nb) * HEADS + h] = reds[nb * 8 + 2 * h] + reds[nb * 8 + 2 * h + 1];
            g_ad[(n0 + nb) * HEADS + h] = redd[nb * 8 + 2 * h] + redd[nb * 8 + 2 * h + 1];
        }
        __syncthreads();
    }
}

// ---------------- K2: per-edge alpha -> exp -> denom accumulation ----------------
__global__ void __launch_bounds__(256) k_edge_alpha(const float* __restrict__ ea) {
    int e = blockIdx.x * blockDim.x + threadIdx.x;
    if (e >= N_EDGES) return;
    const int s = g_src[e];
    const int d = g_dst[e];
    const float4 as4 = *(const float4*)(g_as + s * 4);
    const float4 ad4 = *(const float4*)(g_ad + d * 4);
    const float e0 = ea[(size_t)e * 3];
    const float e1 = ea[(size_t)e * 3 + 1];
    const float e2 = ea[(size_t)e * 3 + 2];

    float a0 = as4.x + ad4.x + e0 * g_M[0] + e1 * g_M[4] + e2 * g_M[8];
    float a1 = as4.y + ad4.y + e0 * g_M[1] + e1 * g_M[5] + e2 * g_M[9];
    float a2 = as4.z + ad4.z + e0 * g_M[2] + e1 * g_M[6] + e2 * g_M[10];
    float a3 = as4.w + ad4.w + e0 * g_M[3] + e1 * g_M[7] + e2 * g_M[11];
    a0 = (a0 < 0.f) ? NEG_SLOPE * a0 : a0;
    a1 = (a1 < 0.f) ? NEG_SLOPE * a1 : a1;
    a2 = (a2 < 0.f) ? NEG_SLOPE * a2 : a2;
    a3 = (a3 < 0.f) ? NEG_SLOPE * a3 : a3;
    // softmax is shift-invariant; alpha is O(10) here so exp() cannot overflow:
    // skip the segment-max pass entirely.
    float4 ex = make_float4(__expf(a0), __expf(a1), __expf(a2), __expf(a3));
    *(float4*)(g_ex + (size_t)e * 4) = ex;
    red_add_v4(g_denom + d * 4, ex);
}

// ---------------- K3: per-edge message scatter ----------------
// 64 threads per edge, each handles one float4 of the 256-wide row.
__global__ void __launch_bounds__(256) k_edge_msg() {
    const int t = threadIdx.x;
    const int lane = t & 63;
    const int e = blockIdx.x * 4 + (t >> 6);
    const int s = g_src[e];
    const int d = g_dst[e];
    const float4 ex = *(const float4*)(g_ex + (size_t)e * 4);
    const float4 dn = *(const float4*)(g_denom + d * 4);
    const int h = lane >> 4;   // head of this float4
    float exv = (h < 2) ? ((h == 0) ? ex.x : ex.y) : ((h == 2) ? ex.z : ex.w);
    float dnv = (h < 2) ? ((h == 0) ? dn.x : dn.y) : ((h == 2) ? dn.z : dn.w);
    const float c = exv / (dnv + 1e-16f);
    const float4 xv = *(const float4*)(g_x + (size_t)s * HC + lane * 4);
    red_add_v4(g_acc + (size_t)d * HC + lane * 4,
               make_float4(c * xv.x, c * xv.y, c * xv.z, c * xv.w));
}

// ---------------- K4: head-mean + bias + LayerNorm + SiLU ----------------
__global__ void __launch_bounds__(256) k_finalize(
    float* __restrict__ zout, const float* __restrict__ bias,
    const float* __restrict__ gamma, const float* __restrict__ beta)
{
    const int t = threadIdx.x;
    const int lane = t & 63;
    const int nloc = t >> 6;
    const int n = blockIdx.x * 4 + nloc;
    const float* a = g_acc + (size_t)n * HC;
    float v = 0.25f * (a[lane] + a[lane + 64] + a[lane + 128] + a[lane + 192]) + bias[lane];

    __shared__ float ws[8], ws2[8];
    float s = v;
#pragma unroll
    for (int o = 16; o; o >>= 1) s += __shfl_xor_sync(0xffffffffu, s, o);
    if ((t & 31) == 0) ws[t >> 5] = s;
    __syncthreads();
    const float mu = (ws[nloc * 2] + ws[nloc * 2 + 1]) * (1.f / 64.f);
    const float dv = v - mu;
    float q = dv * dv;
#pragma unroll
    for (int o = 16; o; o >>= 1) q += __shfl_xor_sync(0xffffffffu, q, o);
    if ((t & 31) == 0) ws2[t >> 5] = q;
    __syncthreads();
    const float var = (ws2[nloc * 2] + ws2[nloc * 2 + 1]) * (1.f / 64.f);
    float y = dv * rsqrtf(var + LN_EPS) * gamma[lane] + beta[lane];
    zout[(size_t)n * HID + lane] = y / (1.f + __expf(-y));
}

// ---------------- launcher ----------------
extern "C" void kernel_launch(void* const* d_in, const int* in_sizes, int n_in,
                              void* d_out, int out_size) {
    (void)in_sizes; (void)n_in; (void)out_size;
    const float* h     = (const float*)d_in[1];
    const void*  ei    = d_in[2];
    const float* ea    = (const float*)d_in[3];
    const float* W     = (const float*)d_in[4];
    const float* We    = (const float*)d_in[5];
    const float* as_   = (const float*)d_in[6];
    const float* ad_   = (const float*)d_in[7];
    const float* ae_   = (const float*)d_in[8];
    const float* bias  = (const float*)d_in[9];
    const float* gamma = (const float*)d_in[10];
    const float* beta  = (const float*)d_in[11];
    float* out = (float*)d_out;

    const int smem_bytes = 17024 * 4;   // 68096 B
    cudaFuncSetAttribute(k_node_proj, cudaFuncAttributeMaxDynamicSharedMemorySize, smem_bytes);

    float* zbuf = nullptr;
    cudaGetSymbolAddress((void**)&zbuf, g_z);

    k_detect<<<1, 1>>>((const int*)ei);
    k_convert<<<(N_EDGES + 255) / 256, 256>>>(ei);

    const float* zin = h;
    for (int l = 0; l < L_LAYERS; l++) {
        k_zero<<<2048, 256>>>();
        k_M<<<1, 32>>>(We + (size_t)l * 3 * HC, ae_ + (size_t)l * HC);
        k_node_proj<<<444, 256, smem_bytes>>>(zin, W + (size_t)l * HID * HC,
                                              as_ + (size_t)l * HC, ad_ + (size_t)l * HC);
        k_edge_alpha<<<(N_EDGES + 255) / 256, 256>>>(ea);
        k_edge_msg<<<N_EDGES / 4, 256>>>();
        k_finalize<<<N_NODES / 4, 256>>>(l == 0 ? zbuf : out,
                                         bias + (size_t)l * HID,
                                         gamma + (size_t)l * HID,
                                         beta + (size_t)l * HID);
        zin = zbuf;
    }
}

// round 2
// speedup vs baseline: 1.7641x; 1.7641x over previous
#include <cuda_runtime.h>
#include <cuda_bf16.h>
#include <cstdint>

#define N_NODES 50000
#define N_EDGES 800000
#define HID 64
#define HEADS 4
#define CDIM 64
#define HC 256   // HEADS*CDIM
#define L_LAYERS 2
#define NEG_SLOPE 0.2f
#define LN_EPS 1e-5f

// ---------------- device scratch (no allocations allowed) ----------------
__device__ float g_x[(size_t)N_NODES * HC];       // projected nodes [N,256]
__device__ float g_acc[(size_t)N_NODES * HID];    // combined-head accumulator [N,64]
__device__ float g_as[N_NODES * HEADS];           // alpha_src [N,4]
__device__ float g_ad[N_NODES * HEADS];           // alpha_dst [N,4]
__device__ float g_denom[N_NODES * HEADS];        // softmax denom [N,4]
__device__ float g_ex[(size_t)N_EDGES * HEADS];   // exp(alpha) per edge [E,4]
__device__ float g_z[(size_t)N_NODES * HID];      // inter-layer activations
__device__ int   g_src[N_EDGES];
__device__ int   g_dst[N_EDGES];
__device__ float g_M[12];                         // edge-attr dual matrix [3][4]
__device__ int   g_is64;

// ---------------- helpers ----------------
__device__ __forceinline__ void red_add_v4(float* addr, float4 v) {
    asm volatile("red.global.add.v4.f32 [%0], {%1,%2,%3,%4};"
                 :: "l"(addr), "f"(v.x), "f"(v.y), "f"(v.z), "f"(v.w) : "memory");
}

// ---------------- K0a: detect edge_index dtype ----------------
__global__ void k_detect(const int* __restrict__ ei32) {
    int zeros = 0;
    for (int i = 1; i < 256; i += 2) if (ei32[i] == 0) zeros++;
    g_is64 = (zeros > 100) ? 1 : 0;   // int64 data: high words all zero
}

// ---------------- K0b: normalize edge index to int32 src/dst ----------------
__global__ void k_convert(const void* __restrict__ ei) {
    int e = blockIdx.x * blockDim.x + threadIdx.x;
    if (e >= N_EDGES) return;
    if (g_is64) {
        const long long* p = (const long long*)ei;
        g_src[e] = (int)p[e];
        g_dst[e] = (int)p[N_EDGES + e];
    } else {
        const int* p = (const int*)ei;
        g_src[e] = p[e];
        g_dst[e] = p[N_EDGES + e];
    }
}

// ---------------- K0c: zero accumulators ----------------
__global__ void k_zero() {
    const float4 z = make_float4(0.f, 0.f, 0.f, 0.f);
    size_t i = (size_t)blockIdx.x * blockDim.x + threadIdx.x;
    size_t stride = (size_t)gridDim.x * blockDim.x;
    const size_t n_acc4 = (size_t)N_NODES * HID / 4;
    for (size_t j = i; j < n_acc4; j += stride) ((float4*)g_acc)[j] = z;
    const size_t n_dn4 = (size_t)N_NODES * HEADS / 4;
    for (size_t j = i; j < n_dn4; j += stride) ((float4*)g_denom)[j] = z;
}

// ---------------- K0d: M[d][h] = sum_c We[d, h*64+c] * a_e[h, c] ----------------
__global__ void k_M(const float* __restrict__ We, const float* __restrict__ a_e) {
    int t = threadIdx.x;
    if (t < 12) {
        int d = t >> 2, h = t & 3;
        float s = 0.f;
        for (int c = 0; c < CDIM; c++)
            s += We[d * HC + h * CDIM + c] * a_e[h * CDIM + c];
        g_M[t] = s;   // layout g_M[d*4+h]
    }
}

// ---------------- K1: node projection + alpha_src/alpha_dst ----------------
#define NB 8
__global__ void __launch_bounds__(256) k_node_proj(
    const float* __restrict__ z, const float* __restrict__ W,
    const float* __restrict__ a_s, const float* __restrict__ a_d)
{
    extern __shared__ float smem[];
    float* Wsh  = smem;                 // 64*256 = 16384 floats
    float* zshT = smem + 16384;         // [k][nb] transposed, 512 floats
    float* reds = smem + 16896;         // [nb][warp] 64 floats
    float* redd = smem + 16960;         // 64 floats

    const int tid = threadIdx.x;
    for (int i = tid; i < (HID * HC) / 4; i += 256)
        ((float4*)Wsh)[i] = ((const float4*)W)[i];
    const float as = a_s[tid];
    const float ad = a_d[tid];
    __syncthreads();

    const int lane = tid & 31;
    const int wid = tid >> 5;

    for (int g = blockIdx.x; g * NB < N_NODES; g += gridDim.x) {
        const int n0 = g * NB;
        for (int i = tid; i < NB * HID; i += 256) {
            int nb = i >> 6, k = i & 63;
            zshT[k * NB + nb] = z[(size_t)n0 * HID + i];
        }
        __syncthreads();

        float acc[NB];
#pragma unroll
        for (int nb = 0; nb < NB; nb++) acc[nb] = 0.f;

#pragma unroll
        for (int k = 0; k < HID; k++) {
            float w = Wsh[k * HC + tid];
            float4 za = ((float4*)zshT)[k * 2];
            float4 zb = ((float4*)zshT)[k * 2 + 1];
            acc[0] = fmaf(za.x, w, acc[0]);
            acc[1] = fmaf(za.y, w, acc[1]);
            acc[2] = fmaf(za.z, w, acc[2]);
            acc[3] = fmaf(za.w, w, acc[3]);
            acc[4] = fmaf(zb.x, w, acc[4]);
            acc[5] = fmaf(zb.y, w, acc[5]);
            acc[6] = fmaf(zb.z, w, acc[6]);
            acc[7] = fmaf(zb.w, w, acc[7]);
        }

#pragma unroll
        for (int nb = 0; nb < NB; nb++)
            g_x[(size_t)(n0 + nb) * HC + tid] = acc[nb];

#pragma unroll
        for (int nb = 0; nb < NB; nb++) {
            float ps = acc[nb] * as;
            float pd = acc[nb] * ad;
#pragma unroll
            for (int o = 16; o; o >>= 1) {
                ps += __shfl_down_sync(0xffffffffu, ps, o);
                pd += __shfl_down_sync(0xffffffffu, pd, o);
            }
            if (lane == 0) { reds[nb * 8 + wid] = ps; redd[nb * 8 + wid] = pd; }
        }
        __syncthreads();
        if (tid < 32) {
            int nb = tid >> 2, h = tid & 3;
            g_as[(n0 + nb) * HEADS + h] = reds[nb * 8 + 2 * h] + reds[nb * 8 + 2 * h + 1];
            g_ad[(n0 + nb) * HEADS + h] = redd[nb * 8 + 2 * h] + redd[nb * 8 + 2 * h + 1];
        }
        __syncthreads();
    }
}

// ---------------- K2: per-edge alpha -> exp -> denom accumulation ----------------
__global__ void __launch_bounds__(256) k_edge_alpha(const float* __restrict__ ea) {
    int e = blockIdx.x * blockDim.x + threadIdx.x;
    if (e >= N_EDGES) return;
    const int s = g_src[e];
    const int d = g_dst[e];
    const float4 as4 = *(const float4*)(g_as + s * 4);
    const float4 ad4 = *(const float4*)(g_ad + d * 4);
    const float e0 = ea[(size_t)e * 3];
    const float e1 = ea[(size_t)e * 3 + 1];
    const float e2 = ea[(size_t)e * 3 + 2];

    float a0 = as4.x + ad4.x + e0 * g_M[0] + e1 * g_M[4] + e2 * g_M[8];
    float a1 = as4.y + ad4.y + e0 * g_M[1] + e1 * g_M[5] + e2 * g_M[9];
    float a2 = as4.z + ad4.z + e0 * g_M[2] + e1 * g_M[6] + e2 * g_M[10];
    float a3 = as4.w + ad4.w + e0 * g_M[3] + e1 * g_M[7] + e2 * g_M[11];
    a0 = (a0 < 0.f) ? NEG_SLOPE * a0 : a0;
    a1 = (a1 < 0.f) ? NEG_SLOPE * a1 : a1;
    a2 = (a2 < 0.f) ? NEG_SLOPE * a2 : a2;
    a3 = (a3 < 0.f) ? NEG_SLOPE * a3 : a3;
    // softmax is shift-invariant; alpha is O(10) here so exp() cannot overflow:
    // skip the segment-max pass entirely.
    float4 ex = make_float4(__expf(a0), __expf(a1), __expf(a2), __expf(a3));
    *(float4*)(g_ex + (size_t)e * 4) = ex;
    red_add_v4(g_denom + d * 4, ex);
}

// ---------------- K3: per-edge message scatter, heads combined ----------------
// Head-mean commutes with segment-sum: scatter m[c] = sum_h c_h * x[src,h,c]
// (64 floats/edge instead of 256). 16 threads per edge, each owns 4 c's.
__global__ void __launch_bounds__(256) k_edge_msg() {
    const int t = threadIdx.x;
    const int q = t & 15;                        // c-chunk index (0..15)
    const int e = blockIdx.x * 16 + (t >> 4);
    const int lane = t & 31;
    const int s = g_src[e];
    const int d = g_dst[e];

    // leader lane of each 16-lane group computes the 4 normalized coefficients
    float c0 = 0.f, c1 = 0.f, c2 = 0.f, c3 = 0.f;
    if ((lane & 15) == 0) {
        const float4 ex = *(const float4*)(g_ex + (size_t)e * 4);
        const float4 dn = *(const float4*)(g_denom + d * 4);
        c0 = __fdividef(ex.x, dn.x + 1e-16f);
        c1 = __fdividef(ex.y, dn.y + 1e-16f);
        c2 = __fdividef(ex.z, dn.z + 1e-16f);
        c3 = __fdividef(ex.w, dn.w + 1e-16f);
    }
    const int srcl = lane & 16;
    c0 = __shfl_sync(0xffffffffu, c0, srcl);
    c1 = __shfl_sync(0xffffffffu, c1, srcl);
    c2 = __shfl_sync(0xffffffffu, c2, srcl);
    c3 = __shfl_sync(0xffffffffu, c3, srcl);

    const float4* xr = (const float4*)(g_x + (size_t)s * HC);
    const float4 x0 = xr[q];          // head 0, c's [4q..4q+3]
    const float4 x1 = xr[16 + q];     // head 1
    const float4 x2 = xr[32 + q];     // head 2
    const float4 x3 = xr[48 + q];     // head 3

    float4 m;
    m.x = c0 * x0.x + c1 * x1.x + c2 * x2.x + c3 * x3.x;
    m.y = c0 * x0.y + c1 * x1.y + c2 * x2.y + c3 * x3.y;
    m.z = c0 * x0.z + c1 * x1.z + c2 * x2.z + c3 * x3.z;
    m.w = c0 * x0.w + c1 * x1.w + c2 * x2.w + c3 * x3.w;

    red_add_v4(g_acc + (size_t)d * HID + q * 4, m);
}

// ---------------- K4: head-mean + bias + LayerNorm + SiLU ----------------
__global__ void __launch_bounds__(256) k_finalize(
    float* __restrict__ zout, const float* __restrict__ bias,
    const float* __restrict__ gamma, const float* __restrict__ beta)
{
    const int t = threadIdx.x;
    const int lane = t & 63;
    const int nloc = t >> 6;
    const int n = blockIdx.x * 4 + nloc;
    float v = 0.25f * g_acc[(size_t)n * HID + lane] + bias[lane];

    __shared__ float ws[8], ws2[8];
    float s = v;
#pragma unroll
    for (int o = 16; o; o >>= 1) s += __shfl_xor_sync(0xffffffffu, s, o);
    if ((t & 31) == 0) ws[t >> 5] = s;
    __syncthreads();
    const float mu = (ws[nloc * 2] + ws[nloc * 2 + 1]) * (1.f / 64.f);
    const float dv = v - mu;
    float q = dv * dv;
#pragma unroll
    for (int o = 16; o; o >>= 1) q += __shfl_xor_sync(0xffffffffu, q, o);
    if ((t & 31) == 0) ws2[t >> 5] = q;
    __syncthreads();
    const float var = (ws2[nloc * 2] + ws2[nloc * 2 + 1]) * (1.f / 64.f);
    float y = dv * rsqrtf(var + LN_EPS) * gamma[lane] + beta[lane];
    zout[(size_t)n * HID + lane] = y / (1.f + __expf(-y));
}

// ---------------- launcher ----------------
extern "C" void kernel_launch(void* const* d_in, const int* in_sizes, int n_in,
                              void* d_out, int out_size) {
    (void)in_sizes; (void)n_in; (void)out_size;
    const float* h     = (const float*)d_in[1];
    const void*  ei    = d_in[2];
    const float* ea    = (const float*)d_in[3];
    const float* W     = (const float*)d_in[4];
    const float* We    = (const float*)d_in[5];
    const float* as_   = (const float*)d_in[6];
    const float* ad_   = (const float*)d_in[7];
    const float* ae_   = (const float*)d_in[8];
    const float* bias  = (const float*)d_in[9];
    const float* gamma = (const float*)d_in[10];
    const float* beta  = (const float*)d_in[11];
    float* out = (float*)d_out;

    const int smem_bytes = 17024 * 4;   // 68096 B
    cudaFuncSetAttribute(k_node_proj, cudaFuncAttributeMaxDynamicSharedMemorySize, smem_bytes);

    float* zbuf = nullptr;
    cudaGetSymbolAddress((void**)&zbuf, g_z);

    k_detect<<<1, 1>>>((const int*)ei);
    k_convert<<<(N_EDGES + 255) / 256, 256>>>(ei);

    const float* zin = h;
    for (int l = 0; l < L_LAYERS; l++) {
        k_zero<<<1024, 256>>>();
        k_M<<<1, 32>>>(We + (size_t)l * 3 * HC, ae_ + (size_t)l * HC);
        k_node_proj<<<444, 256, smem_bytes>>>(zin, W + (size_t)l * HID * HC,
                                              as_ + (size_t)l * HC, ad_ + (size_t)l * HC);
        k_edge_alpha<<<(N_EDGES + 255) / 256, 256>>>(ea);
        k_edge_msg<<<N_EDGES / 16, 256>>>();
        k_finalize<<<N_NODES / 4, 256>>>(l == 0 ? zbuf : out,
                                         bias + (size_t)l * HID,
                                         gamma + (size_t)l * HID,
                                         beta + (size_t)l * HID);
        zin = zbuf;
    }
}

// round 5
// speedup vs baseline: 1.8247x; 1.0343x over previous
#include <cuda_runtime.h>
#include <cuda_bf16.h>
#include <cstdint>

#define N_NODES 50000
#define N_EDGES 800000
#define HID 64
#define HEADS 4
#define CDIM 64
#define HC 256   // HEADS*CDIM
#define L_LAYERS 2
#define NEG_SLOPE 0.2f
#define LN_EPS 1e-5f

// ---------------- device scratch (no allocations allowed) ----------------
__device__ float g_x[(size_t)N_NODES * HC];       // projected nodes [N,256]
__device__ float g_as[N_NODES * HEADS];           // alpha_src [N,4]
__device__ float g_ad[N_NODES * HEADS];           // alpha_dst [N,4]
__device__ float g_exs[(size_t)N_EDGES * HEADS];  // exp(alpha), CSR order [E,4]
__device__ float g_z[(size_t)N_NODES * HID];      // inter-layer activations
__device__ int   g_src[N_EDGES];
__device__ int   g_dst[N_EDGES];
__device__ int   g_pos[N_EDGES];                  // orig edge -> CSR slot
__device__ int   g_csr_src[N_EDGES];              // src id per CSR slot
__device__ int   g_rowptr[N_NODES + 1];
__device__ int   g_cur[N_NODES];
__device__ int   g_deg[N_NODES];
__device__ float g_M[12];                         // edge-attr dual matrix [3][4]
__device__ int   g_is64;

// ---------------- K0a: detect edge_index dtype ----------------
__global__ void k_detect(const int* __restrict__ ei32) {
    int zeros = 0;
    for (int i = 1; i < 256; i += 2) if (ei32[i] == 0) zeros++;
    g_is64 = (zeros > 100) ? 1 : 0;   // int64 data: high words all zero
}

// ---------------- K0b: zero degrees ----------------
__global__ void k_zero_deg() {
    int i = blockIdx.x * blockDim.x + threadIdx.x;
    if (i < N_NODES) g_deg[i] = 0;
}

// ---------------- K0c: normalize edge index + count degrees ----------------
__global__ void k_convert(const void* __restrict__ ei) {
    int e = blockIdx.x * blockDim.x + threadIdx.x;
    if (e >= N_EDGES) return;
    int s, d;
    if (g_is64) {
        const long long* p = (const long long*)ei;
        s = (int)p[e]; d = (int)p[N_EDGES + e];
    } else {
        const int* p = (const int*)ei;
        s = p[e]; d = p[N_EDGES + e];
    }
    g_src[e] = s;
    g_dst[e] = d;
    atomicAdd(&g_deg[d], 1);
}

// ---------------- K0d: single-block exclusive scan deg -> rowptr ----------------
__global__ void __launch_bounds__(1024) k_scan() {
    __shared__ int warp_sums[32];
    __shared__ int s_carry;
    const int tid = threadIdx.x;
    if (tid == 0) s_carry = 0;
    __syncthreads();
    for (int base = 0; base < N_NODES; base += 1024) {
        const int i = base + tid;
        const int v = (i < N_NODES) ? g_deg[i] : 0;
        int x = v;
#pragma unroll
        for (int o = 1; o < 32; o <<= 1) {
            int y = __shfl_up_sync(0xffffffffu, x, o);
            if ((tid & 31) >= o) x += y;
        }
        if ((tid & 31) == 31) warp_sums[tid >> 5] = x;
        __syncthreads();
        if (tid < 32) {
            int w = warp_sums[tid];
#pragma unroll
            for (int o = 1; o < 32; o <<= 1) {
                int y = __shfl_up_sync(0xffffffffu, w, o);
                if (tid >= o) w += y;
            }
            warp_sums[tid] = w;
        }
        __syncthreads();
        int excl = x - v + s_carry + ((tid >= 32) ? warp_sums[(tid >> 5) - 1] : 0);
        if (i < N_NODES) { g_rowptr[i] = excl; g_cur[i] = excl; }
        int total_in = warp_sums[31];
        __syncthreads();
        if (tid == 0) s_carry += total_in;
        __syncthreads();
    }
    if (tid == 0) g_rowptr[N_NODES] = s_carry;
}

// ---------------- K0e: fill CSR ----------------
__global__ void k_fill() {
    int e = blockIdx.x * blockDim.x + threadIdx.x;
    if (e >= N_EDGES) return;
    int d = g_dst[e];
    int pos = atomicAdd(&g_cur[d], 1);
    g_csr_src[pos] = g_src[e];
    g_pos[e] = pos;
}

// ---------------- K0f: M[d][h] = sum_c We[d, h*64+c] * a_e[h, c] ----------------
__global__ void k_M(const float* __restrict__ We, const float* __restrict__ a_e) {
    int t = threadIdx.x;
    if (t < 12) {
        int d = t >> 2, h = t & 3;
        float s = 0.f;
        for (int c = 0; c < CDIM; c++)
            s += We[d * HC + h * CDIM + c] * a_e[h * CDIM + c];
        g_M[t] = s;   // layout g_M[d*4+h]
    }
}

// ---------------- K1: node projection + alpha_src/alpha_dst ----------------
#define NB 8
__global__ void __launch_bounds__(256) k_node_proj(
    const float* __restrict__ z, const float* __restrict__ W,
    const float* __restrict__ a_s, const float* __restrict__ a_d)
{
    extern __shared__ float smem[];
    float* Wsh  = smem;                 // 64*256 = 16384 floats
    float* zshT = smem + 16384;         // [k][nb] transposed, 512 floats
    float* reds = smem + 16896;         // 64 floats
    float* redd = smem + 16960;         // 64 floats

    const int tid = threadIdx.x;
    for (int i = tid; i < (HID * HC) / 4; i += 256)
        ((float4*)Wsh)[i] = ((const float4*)W)[i];
    const float as = a_s[tid];
    const float ad = a_d[tid];
    __syncthreads();

    const int lane = tid & 31;
    const int wid = tid >> 5;
    const int nblocks = gridDim.x;

    for (int g = blockIdx.x; g * NB < N_NODES; g += nblocks) {
        const int n0 = g * NB;
        for (int i = tid; i < NB * HID; i += 256) {
            int nb = i >> 6, k = i & 63;
            zshT[k * NB + nb] = z[(size_t)n0 * HID + i];
        }
        __syncthreads();

        float acc[NB];
#pragma unroll
        for (int nb = 0; nb < NB; nb++) acc[nb] = 0.f;

#pragma unroll
        for (int k = 0; k < HID; k++) {
            float w = Wsh[k * HC + tid];
            float4 za = ((float4*)zshT)[k * 2];
            float4 zb = ((float4*)zshT)[k * 2 + 1];
            acc[0] = fmaf(za.x, w, acc[0]);
            acc[1] = fmaf(za.y, w, acc[1]);
            acc[2] = fmaf(za.z, w, acc[2]);
            acc[3] = fmaf(za.w, w, acc[3]);
            acc[4] = fmaf(zb.x, w, acc[4]);
            acc[5] = fmaf(zb.y, w, acc[5]);
            acc[6] = fmaf(zb.z, w, acc[6]);
            acc[7] = fmaf(zb.w, w, acc[7]);
        }

#pragma unroll
        for (int nb = 0; nb < NB; nb++)
            g_x[(size_t)(n0 + nb) * HC + tid] = acc[nb];

#pragma unroll
        for (int nb = 0; nb < NB; nb++) {
            float ps = acc[nb] * as;
            float pd = acc[nb] * ad;
#pragma unroll
            for (int o = 16; o; o >>= 1) {
                ps += __shfl_down_sync(0xffffffffu, ps, o);
                pd += __shfl_down_sync(0xffffffffu, pd, o);
            }
            if (lane == 0) { reds[nb * 8 + wid] = ps; redd[nb * 8 + wid] = pd; }
        }
        __syncthreads();
        if (tid < 32) {
            int nb = tid >> 2, h = tid & 3;
            g_as[(n0 + nb) * HEADS + h] = reds[nb * 8 + 2 * h] + reds[nb * 8 + 2 * h + 1];
            g_ad[(n0 + nb) * HEADS + h] = redd[nb * 8 + 2 * h] + redd[nb * 8 + 2 * h + 1];
        }
        __syncthreads();
    }
}

// ---------------- K2: per-edge alpha -> exp, written in CSR order ----------------
__global__ void __launch_bounds__(256) k_edge_alpha(const float* __restrict__ ea) {
    int e = blockIdx.x * blockDim.x + threadIdx.x;
    if (e >= N_EDGES) return;
    const int s = g_src[e];
    const int d = g_dst[e];
    const float4 as4 = *(const float4*)(g_as + s * 4);
    const float4 ad4 = *(const float4*)(g_ad + d * 4);
    const float e0 = ea[(size_t)e * 3];
    const float e1 = ea[(size_t)e * 3 + 1];
    const float e2 = ea[(size_t)e * 3 + 2];

    float a0 = as4.x + ad4.x + e0 * g_M[0] + e1 * g_M[4] + e2 * g_M[8];
    float a1 = as4.y + ad4.y + e0 * g_M[1] + e1 * g_M[5] + e2 * g_M[9];
    float a2 = as4.z + ad4.z + e0 * g_M[2] + e1 * g_M[6] + e2 * g_M[10];
    float a3 = as4.w + ad4.w + e0 * g_M[3] + e1 * g_M[7] + e2 * g_M[11];
    a0 = (a0 < 0.f) ? NEG_SLOPE * a0 : a0;
    a1 = (a1 < 0.f) ? NEG_SLOPE * a1 : a1;
    a2 = (a2 < 0.f) ? NEG_SLOPE * a2 : a2;
    a3 = (a3 < 0.f) ? NEG_SLOPE * a3 : a3;
    // softmax is shift-invariant and alpha is O(10): skip segment-max entirely.
    float4 ex = make_float4(__expf(a0), __expf(a1), __expf(a2), __expf(a3));
    ((float4*)g_exs)[g_pos[e]] = ex;
}

// ---------------- K3: CSR message pass + finalize (fused) ----------------
// 16 threads per dst node; each owns 4 channels (heads pre-combined).
__global__ void __launch_bounds__(256) k_gat_msg(
    float* __restrict__ zout, const float* __restrict__ bias,
    const float* __restrict__ gamma, const float* __restrict__ beta)
{
    const int t = threadIdx.x;
    const int q = t & 15;
    const int n = blockIdx.x * 16 + (t >> 4);
    const int row0 = g_rowptr[n];
    const int row1 = g_rowptr[n + 1];

    // sweep 1: denominator (parallel over edges within the 16-lane group)
    float4 dn = make_float4(0.f, 0.f, 0.f, 0.f);
    for (int j = row0 + q; j < row1; j += 16) {
        const float4 ex = ((const float4*)g_exs)[j];
        dn.x += ex.x; dn.y += ex.y; dn.z += ex.z; dn.w += ex.w;
    }
#pragma unroll
    for (int o = 8; o; o >>= 1) {
        dn.x += __shfl_xor_sync(0xffffffffu, dn.x, o);
        dn.y += __shfl_xor_sync(0xffffffffu, dn.y, o);
        dn.z += __shfl_xor_sync(0xffffffffu, dn.z, o);
        dn.w += __shfl_xor_sync(0xffffffffu, dn.w, o);
    }
    const float i0 = __frcp_rn(dn.x + 1e-16f);
    const float i1 = __frcp_rn(dn.y + 1e-16f);
    const float i2 = __frcp_rn(dn.z + 1e-16f);
    const float i3 = __frcp_rn(dn.w + 1e-16f);

    // sweep 2: serial over edges (unrolled x2 for MLP), 16 lanes gather x[src]
    float4 accA = make_float4(0.f, 0.f, 0.f, 0.f);
    float4 accB = make_float4(0.f, 0.f, 0.f, 0.f);
    int j = row0;
    for (; j + 1 < row1; j += 2) {
        const int sA = g_csr_src[j];
        const int sB = g_csr_src[j + 1];
        const float4 exA = ((const float4*)g_exs)[j];
        const float4 exB = ((const float4*)g_exs)[j + 1];
        const float4* xrA = (const float4*)(g_x + (size_t)sA * HC);
        const float4* xrB = (const float4*)(g_x + (size_t)sB * HC);
        const float4 a0 = xrA[q],      b0 = xrB[q];
        const float4 a1 = xrA[16 + q], b1 = xrB[16 + q];
        const float4 a2 = xrA[32 + q], b2 = xrB[32 + q];
        const float4 a3 = xrA[48 + q], b3 = xrB[48 + q];
        const float cA0 = exA.x * i0, cA1 = exA.y * i1, cA2 = exA.z * i2, cA3 = exA.w * i3;
        const float cB0 = exB.x * i0, cB1 = exB.y * i1, cB2 = exB.z * i2, cB3 = exB.w * i3;
        accA.x += cA0 * a0.x + cA1 * a1.x + cA2 * a2.x + cA3 * a3.x;
        accA.y += cA0 * a0.y + cA1 * a1.y + cA2 * a2.y + cA3 * a3.y;
        accA.z += cA0 * a0.z + cA1 * a1.z + cA2 * a2.z + cA3 * a3.z;
        accA.w += cA0 * a0.w + cA1 * a1.w + cA2 * a2.w + cA3 * a3.w;
        accB.x += cB0 * b0.x + cB1 * b1.x + cB2 * b2.x + cB3 * b3.x;
        accB.y += cB0 * b0.y + cB1 * b1.y + cB2 * b2.y + cB3 * b3.y;
        accB.z += cB0 * b0.z + cB1 * b1.z + cB2 * b2.z + cB3 * b3.z;
        accB.w += cB0 * b0.w + cB1 * b1.w + cB2 * b2.w + cB3 * b3.w;
    }
    if (j < row1) {
        const int s = g_csr_src[j];
        const float4 ex = ((const float4*)g_exs)[j];
        const float c0 = ex.x * i0, c1 = ex.y * i1, c2 = ex.z * i2, c3 = ex.w * i3;
        const float4* xr = (const float4*)(g_x + (size_t)s * HC);
        const float4 x0 = xr[q];
        const float4 x1 = xr[16 + q];
        const float4 x2 = xr[32 + q];
        const float4 x3 = xr[48 + q];
        accA.x += c0 * x0.x + c1 * x1.x + c2 * x2.x + c3 * x3.x;
        accA.y += c0 * x0.y + c1 * x1.y + c2 * x2.y + c3 * x3.y;
        accA.z += c0 * x0.z + c1 * x1.z + c2 * x2.z + c3 * x3.z;
        accA.w += c0 * x0.w + c1 * x1.w + c2 * x2.w + c3 * x3.w;
    }
    float4 acc;
    acc.x = accA.x + accB.x;
    acc.y = accA.y + accB.y;
    acc.z = accA.z + accB.z;
    acc.w = accA.w + accB.w;

    // finalize: head-mean + bias + LN + SiLU
    float v0 = 0.25f * acc.x + bias[q * 4 + 0];
    float v1 = 0.25f * acc.y + bias[q * 4 + 1];
    float v2 = 0.25f * acc.z + bias[q * 4 + 2];
    float v3 = 0.25f * acc.w + bias[q * 4 + 3];

    float s = v0 + v1 + v2 + v3;
#pragma unroll
    for (int o = 8; o; o >>= 1) s += __shfl_xor_sync(0xffffffffu, s, o);
    const float mu = s * (1.f / 64.f);
    const float d0 = v0 - mu, d1 = v1 - mu, d2 = v2 - mu, d3 = v3 - mu;
    float qs = d0 * d0 + d1 * d1 + d2 * d2 + d3 * d3;
#pragma unroll
    for (int o = 8; o; o >>= 1) qs += __shfl_xor_sync(0xffffffffu, qs, o);
    const float rs = rsqrtf(qs * (1.f / 64.f) + LN_EPS);

    float4 y;
    float g0 = gamma[q * 4 + 0], g1 = gamma[q * 4 + 1], g2 = gamma[q * 4 + 2], g3 = gamma[q * 4 + 3];
    float b0 = beta[q * 4 + 0],  b1 = beta[q * 4 + 1],  b2 = beta[q * 4 + 2],  b3 = beta[q * 4 + 3];
    float t0 = d0 * rs * g0 + b0;
    float t1 = d1 * rs * g1 + b1;
    float t2 = d2 * rs * g2 + b2;
    float t3 = d3 * rs * g3 + b3;
    y.x = t0 / (1.f + __expf(-t0));
    y.y = t1 / (1.f + __expf(-t1));
    y.z = t2 / (1.f + __expf(-t2));
    y.w = t3 / (1.f + __expf(-t3));
    ((float4*)(zout + (size_t)n * HID))[q] = y;
}

// ---------------- launcher ----------------
extern "C" void kernel_launch(void* const* d_in, const int* in_sizes, int n_in,
                              void* d_out, int out_size) {
    (void)in_sizes; (void)n_in; (void)out_size;
    const float* h     = (const float*)d_in[1];
    const void*  ei    = d_in[2];
    const float* ea    = (const float*)d_in[3];
    const float* W     = (const float*)d_in[4];
    const float* We    = (const float*)d_in[5];
    const float* as_   = (const float*)d_in[6];
    const float* ad_   = (const float*)d_in[7];
    const float* ae_   = (const float*)d_in[8];
    const float* bias  = (const float*)d_in[9];
    const float* gamma = (const float*)d_in[10];
    const float* beta  = (const float*)d_in[11];
    float* out = (float*)d_out;

    const int smem_bytes = 17024 * 4;   // 68096 B
    cudaFuncSetAttribute(k_node_proj, cudaFuncAttributeMaxDynamicSharedMemorySize, smem_bytes);

    float* zbuf = nullptr;
    cudaGetSymbolAddress((void**)&zbuf, g_z);

    // ---- preamble: CSR build (edge_index is layer-invariant) ----
    k_detect<<<1, 1>>>((const int*)ei);
    k_zero_deg<<<(N_NODES + 255) / 256, 256>>>();
    k_convert<<<(N_EDGES + 255) / 256, 256>>>(ei);
    k_scan<<<1, 1024>>>();
    k_fill<<<(N_EDGES + 255) / 256, 256>>>();

    const float* zin = h;
    for (int l = 0; l < L_LAYERS; l++) {
        k_M<<<1, 32>>>(We + (size_t)l * 3 * HC, ae_ + (size_t)l * HC);
        k_node_proj<<<444, 256, smem_bytes>>>(zin, W + (size_t)l * HID * HC,
                                              as_ + (size_t)l * HC, ad_ + (size_t)l * HC);
        k_edge_alpha<<<(N_EDGES + 255) / 256, 256>>>(ea);
        k_gat_msg<<<N_NODES / 16, 256>>>(l == 0 ? zbuf : out,
                                         bias + (size_t)l * HID,
                                         gamma + (size_t)l * HID,
                                         beta + (size_t)l * HID);
        zin = zbuf;
    }
}

// round 6
// speedup vs baseline: 2.1055x; 1.1539x over previous
#include <cuda_runtime.h>
#include <cuda_bf16.h>
#include <cstdint>

#define N_NODES 50000
#define N_EDGES 800000
#define HID 64
#define HEADS 4
#define CDIM 64
#define HC 256   // HEADS*CDIM
#define L_LAYERS 2
#define NEG_SLOPE 0.2f
#define LN_EPS 1e-5f
#define SCAN_BLK 1024
#define N_SCAN_BLOCKS ((N_NODES + SCAN_BLK - 1) / SCAN_BLK)   // 49

// ---------------- device scratch (no allocations allowed) ----------------
__device__ float g_x[(size_t)N_NODES * HC];       // projected nodes [N,256]
__device__ float g_as[N_NODES * HEADS];           // alpha_src [N,4]
__device__ float g_ad[N_NODES * HEADS];           // alpha_dst [N,4]
__device__ float g_exs[(size_t)N_EDGES * HEADS];  // exp(alpha), CSR order [E,4]
__device__ float g_ea_csr[(size_t)N_EDGES * 4];   // edge_attr in CSR order [E,4]
__device__ float g_z[(size_t)N_NODES * HID];      // inter-layer activations
__device__ int   g_src[N_EDGES];
__device__ int   g_dst[N_EDGES];
__device__ int   g_csr_src[N_EDGES];              // src id per CSR slot
__device__ int   g_rowptr[N_NODES + 1];
__device__ int   g_cur[N_NODES];
__device__ int   g_deg[N_NODES];
__device__ int   g_bsum[N_SCAN_BLOCKS];
__device__ int   g_boff[N_SCAN_BLOCKS];
__device__ float g_M[12];                         // edge-attr dual matrix [3][4]
__device__ int   g_is64;

// ---------------- K0a: detect dtype + zero degrees (fused) ----------------
__global__ void k_detect_zero(const int* __restrict__ ei32) {
    int i = blockIdx.x * blockDim.x + threadIdx.x;
    if (i < N_NODES) g_deg[i] = 0;
    if (i == 0) {
        int zeros = 0;
        for (int k = 1; k < 256; k += 2) if (ei32[k] == 0) zeros++;
        g_is64 = (zeros > 100) ? 1 : 0;   // int64 data: high words all zero
    }
}

// ---------------- K0b: normalize edge index + count degrees ----------------
__global__ void k_convert(const void* __restrict__ ei) {
    int e = blockIdx.x * blockDim.x + threadIdx.x;
    if (e >= N_EDGES) return;
    int s, d;
    if (g_is64) {
        const long long* p = (const long long*)ei;
        s = (int)p[e]; d = (int)p[N_EDGES + e];
    } else {
        const int* p = (const int*)ei;
        s = p[e]; d = p[N_EDGES + e];
    }
    g_src[e] = s;
    g_dst[e] = d;
    atomicAdd(&g_deg[d], 1);
}

// ---------------- K0c: scan phase A — per-block exclusive scan ----------------
__global__ void __launch_bounds__(SCAN_BLK) k_scanA() {
    __shared__ int warp_sums[32];
    const int tid = threadIdx.x;
    const int i = blockIdx.x * SCAN_BLK + tid;
    const int v = (i < N_NODES) ? g_deg[i] : 0;
    int x = v;
#pragma unroll
    for (int o = 1; o < 32; o <<= 1) {
        int y = __shfl_up_sync(0xffffffffu, x, o);
        if ((tid & 31) >= o) x += y;
    }
    if ((tid & 31) == 31) warp_sums[tid >> 5] = x;
    __syncthreads();
    if (tid < 32) {
        int w = warp_sums[tid];
#pragma unroll
        for (int o = 1; o < 32; o <<= 1) {
            int y = __shfl_up_sync(0xffffffffu, w, o);
            if (tid >= o) w += y;
        }
        warp_sums[tid] = w;
    }
    __syncthreads();
    const int excl = x - v + ((tid >= 32) ? warp_sums[(tid >> 5) - 1] : 0);
    if (i < N_NODES) g_rowptr[i] = excl;
    if (tid == SCAN_BLK - 1) g_bsum[blockIdx.x] = excl + v;
}

// ---------------- K0d: scan phase B — scan the 49 block sums ----------------
__global__ void k_scanB() {
    __shared__ int s0;
    const int tid = threadIdx.x;   // 64 threads
    const int v = (tid < N_SCAN_BLOCKS) ? g_bsum[tid] : 0;
    int x = v;
#pragma unroll
    for (int o = 1; o < 32; o <<= 1) {
        int y = __shfl_up_sync(0xffffffffu, x, o);
        if ((tid & 31) >= o) x += y;
    }
    if (tid == 31) s0 = x;
    __syncthreads();
    if (tid >= 32) x += s0;
    if (tid < N_SCAN_BLOCKS) g_boff[tid] = x - v;
    if (tid == N_SCAN_BLOCKS - 1) g_rowptr[N_NODES] = x;
}

// ---------------- K0e: scan phase C — add block offsets ----------------
__global__ void __launch_bounds__(SCAN_BLK) k_scanC() {
    const int i = blockIdx.x * SCAN_BLK + threadIdx.x;
    if (i < N_NODES) {
        const int r = g_rowptr[i] + g_boff[blockIdx.x];
        g_rowptr[i] = r;
        g_cur[i] = r;
    }
}

// ---------------- K0f: fill CSR (src id + edge_attr gathered to CSR order) ----------------
__global__ void k_fill(const float* __restrict__ ea) {
    int e = blockIdx.x * blockDim.x + threadIdx.x;
    if (e >= N_EDGES) return;
    int d = g_dst[e];
    int pos = atomicAdd(&g_cur[d], 1);
    g_csr_src[pos] = g_src[e];
    const float* p = ea + (size_t)e * 3;
    ((float4*)g_ea_csr)[pos] = make_float4(p[0], p[1], p[2], 0.f);
}

// ---------------- K0g: M[d][h] = sum_c We[d, h*64+c] * a_e[h, c] ----------------
__global__ void k_M(const float* __restrict__ We, const float* __restrict__ a_e) {
    int t = threadIdx.x;
    if (t < 12) {
        int d = t >> 2, h = t & 3;
        float s = 0.f;
        for (int c = 0; c < CDIM; c++)
            s += We[d * HC + h * CDIM + c] * a_e[h * CDIM + c];
        g_M[t] = s;   // layout g_M[d*4+h]
    }
}

// ---------------- K1: node projection + alpha_src/alpha_dst ----------------
#define NB 8
__global__ void __launch_bounds__(256) k_node_proj(
    const float* __restrict__ z, const float* __restrict__ W,
    const float* __restrict__ a_s, const float* __restrict__ a_d)
{
    extern __shared__ float smem[];
    float* Wsh  = smem;                 // 64*256 = 16384 floats
    float* zshT = smem + 16384;         // [k][nb] transposed, 512 floats
    float* reds = smem + 16896;         // 64 floats
    float* redd = smem + 16960;         // 64 floats

    const int tid = threadIdx.x;
    for (int i = tid; i < (HID * HC) / 4; i += 256)
        ((float4*)Wsh)[i] = ((const float4*)W)[i];
    const float as = a_s[tid];
    const float ad = a_d[tid];
    __syncthreads();

    const int lane = tid & 31;
    const int wid = tid >> 5;
    const int nblocks = gridDim.x;

    for (int g = blockIdx.x; g * NB < N_NODES; g += nblocks) {
        const int n0 = g * NB;
        for (int i = tid; i < NB * HID; i += 256) {
            int nb = i >> 6, k = i & 63;
            zshT[k * NB + nb] = z[(size_t)n0 * HID + i];
        }
        __syncthreads();

        float acc[NB];
#pragma unroll
        for (int nb = 0; nb < NB; nb++) acc[nb] = 0.f;

#pragma unroll
        for (int k = 0; k < HID; k++) {
            float w = Wsh[k * HC + tid];
            float4 za = ((float4*)zshT)[k * 2];
            float4 zb = ((float4*)zshT)[k * 2 + 1];
            acc[0] = fmaf(za.x, w, acc[0]);
            acc[1] = fmaf(za.y, w, acc[1]);
            acc[2] = fmaf(za.z, w, acc[2]);
            acc[3] = fmaf(za.w, w, acc[3]);
            acc[4] = fmaf(zb.x, w, acc[4]);
            acc[5] = fmaf(zb.y, w, acc[5]);
            acc[6] = fmaf(zb.z, w, acc[6]);
            acc[7] = fmaf(zb.w, w, acc[7]);
        }

#pragma unroll
        for (int nb = 0; nb < NB; nb++)
            g_x[(size_t)(n0 + nb) * HC + tid] = acc[nb];

#pragma unroll
        for (int nb = 0; nb < NB; nb++) {
            float ps = acc[nb] * as;
            float pd = acc[nb] * ad;
#pragma unroll
            for (int o = 16; o; o >>= 1) {
                ps += __shfl_down_sync(0xffffffffu, ps, o);
                pd += __shfl_down_sync(0xffffffffu, pd, o);
            }
            if (lane == 0) { reds[nb * 8 + wid] = ps; redd[nb * 8 + wid] = pd; }
        }
        __syncthreads();
        if (tid < 32) {
            int nb = tid >> 2, h = tid & 3;
            g_as[(n0 + nb) * HEADS + h] = reds[nb * 8 + 2 * h] + reds[nb * 8 + 2 * h + 1];
            g_ad[(n0 + nb) * HEADS + h] = redd[nb * 8 + 2 * h] + redd[nb * 8 + 2 * h + 1];
        }
        __syncthreads();
    }
}

// ---------------- K2: fused alpha + CSR message pass + finalize ----------------
// 16 threads per dst node; each lane owns 4 channels (heads pre-combined).
__global__ void __launch_bounds__(256) k_gat_msg(
    float* __restrict__ zout, const float* __restrict__ bias,
    const float* __restrict__ gamma, const float* __restrict__ beta)
{
    const int t = threadIdx.x;
    const int q = t & 15;
    const int n = blockIdx.x * 16 + (t >> 4);
    const int row0 = g_rowptr[n];
    const int row1 = g_rowptr[n + 1];

    const float4 ad4 = *(const float4*)(g_ad + n * 4);
    const float M0 = g_M[0], M1 = g_M[1], M2  = g_M[2],  M3  = g_M[3];
    const float M4 = g_M[4], M5 = g_M[5], M6  = g_M[6],  M7  = g_M[7];
    const float M8 = g_M[8], M9 = g_M[9], M10 = g_M[10], M11 = g_M[11];

    // sweep 1: compute alpha->exp per edge (lane-strided), accumulate denom,
    // store ex to g_exs in coalesced CSR order.
    float4 dn = make_float4(0.f, 0.f, 0.f, 0.f);
    for (int j = row0 + q; j < row1; j += 16) {
        const int s = g_csr_src[j];
        const float4 as4 = *(const float4*)(g_as + s * 4);
        const float4 ea4 = ((const float4*)g_ea_csr)[j];
        float a0 = as4.x + ad4.x + ea4.x * M0 + ea4.y * M4 + ea4.z * M8;
        float a1 = as4.y + ad4.y + ea4.x * M1 + ea4.y * M5 + ea4.z * M9;
        float a2 = as4.z + ad4.z + ea4.x * M2 + ea4.y * M6 + ea4.z * M10;
        float a3 = as4.w + ad4.w + ea4.x * M3 + ea4.y * M7 + ea4.z * M11;
        a0 = (a0 < 0.f) ? NEG_SLOPE * a0 : a0;
        a1 = (a1 < 0.f) ? NEG_SLOPE * a1 : a1;
        a2 = (a2 < 0.f) ? NEG_SLOPE * a2 : a2;
        a3 = (a3 < 0.f) ? NEG_SLOPE * a3 : a3;
        // softmax shift-invariance + alpha ~ O(10): segment-max pass skipped.
        const float4 ex = make_float4(__expf(a0), __expf(a1), __expf(a2), __expf(a3));
        ((float4*)g_exs)[j] = ex;
        dn.x += ex.x; dn.y += ex.y; dn.z += ex.z; dn.w += ex.w;
    }
#pragma unroll
    for (int o = 8; o; o >>= 1) {
        dn.x += __shfl_xor_sync(0xffffffffu, dn.x, o);
        dn.y += __shfl_xor_sync(0xffffffffu, dn.y, o);
        dn.z += __shfl_xor_sync(0xffffffffu, dn.z, o);
        dn.w += __shfl_xor_sync(0xffffffffu, dn.w, o);
    }
    const float i0 = __frcp_rn(dn.x + 1e-16f);
    const float i1 = __frcp_rn(dn.y + 1e-16f);
    const float i2 = __frcp_rn(dn.z + 1e-16f);
    const float i3 = __frcp_rn(dn.w + 1e-16f);
    __syncwarp();   // order g_exs stores before cross-lane readback

    // sweep 2: serial over edges (unrolled x2 for MLP), 16 lanes gather x[src]
    float4 accA = make_float4(0.f, 0.f, 0.f, 0.f);
    float4 accB = make_float4(0.f, 0.f, 0.f, 0.f);
    int j = row0;
    for (; j + 1 < row1; j += 2) {
        const int sA = g_csr_src[j];
        const int sB = g_csr_src[j + 1];
        const float4 exA = ((const float4*)g_exs)[j];
        const float4 exB = ((const float4*)g_exs)[j + 1];
        const float4* xrA = (const float4*)(g_x + (size_t)sA * HC);
        const float4* xrB = (const float4*)(g_x + (size_t)sB * HC);
        const float4 a0 = xrA[q],      b0 = xrB[q];
        const float4 a1 = xrA[16 + q], b1 = xrB[16 + q];
        const float4 a2 = xrA[32 + q], b2 = xrB[32 + q];
        const float4 a3 = xrA[48 + q], b3 = xrB[48 + q];
        const float cA0 = exA.x * i0, cA1 = exA.y * i1, cA2 = exA.z * i2, cA3 = exA.w * i3;
        const float cB0 = exB.x * i0, cB1 = exB.y * i1, cB2 = exB.z * i2, cB3 = exB.w * i3;
        accA.x += cA0 * a0.x + cA1 * a1.x + cA2 * a2.x + cA3 * a3.x;
        accA.y += cA0 * a0.y + cA1 * a1.y + cA2 * a2.y + cA3 * a3.y;
        accA.z += cA0 * a0.z + cA1 * a1.z + cA2 * a2.z + cA3 * a3.z;
        accA.w += cA0 * a0.w + cA1 * a1.w + cA2 * a2.w + cA3 * a3.w;
        accB.x += cB0 * b0.x + cB1 * b1.x + cB2 * b2.x + cB3 * b3.x;
        accB.y += cB0 * b0.y + cB1 * b1.y + cB2 * b2.y + cB3 * b3.y;
        accB.z += cB0 * b0.z + cB1 * b1.z + cB2 * b2.z + cB3 * b3.z;
        accB.w += cB0 * b0.w + cB1 * b1.w + cB2 * b2.w + cB3 * b3.w;
    }
    if (j < row1) {
        const int s = g_csr_src[j];
        const float4 ex = ((const float4*)g_exs)[j];
        const float c0 = ex.x * i0, c1 = ex.y * i1, c2 = ex.z * i2, c3 = ex.w * i3;
        const float4* xr = (const float4*)(g_x + (size_t)s * HC);
        const float4 x0 = xr[q];
        const float4 x1 = xr[16 + q];
        const float4 x2 = xr[32 + q];
        const float4 x3 = xr[48 + q];
        accA.x += c0 * x0.x + c1 * x1.x + c2 * x2.x + c3 * x3.x;
        accA.y += c0 * x0.y + c1 * x1.y + c2 * x2.y + c3 * x3.y;
        accA.z += c0 * x0.z + c1 * x1.z + c2 * x2.z + c3 * x3.z;
        accA.w += c0 * x0.w + c1 * x1.w + c2 * x2.w + c3 * x3.w;
    }
    float4 acc;
    acc.x = accA.x + accB.x;
    acc.y = accA.y + accB.y;
    acc.z = accA.z + accB.z;
    acc.w = accA.w + accB.w;

    // finalize: head-mean + bias + LN + SiLU
    float v0 = 0.25f * acc.x + bias[q * 4 + 0];
    float v1 = 0.25f * acc.y + bias[q * 4 + 1];
    float v2 = 0.25f * acc.z + bias[q * 4 + 2];
    float v3 = 0.25f * acc.w + bias[q * 4 + 3];

    float s = v0 + v1 + v2 + v3;
#pragma unroll
    for (int o = 8; o; o >>= 1) s += __shfl_xor_sync(0xffffffffu, s, o);
    const float mu = s * (1.f / 64.f);
    const float d0 = v0 - mu, d1 = v1 - mu, d2 = v2 - mu, d3 = v3 - mu;
    float qs = d0 * d0 + d1 * d1 + d2 * d2 + d3 * d3;
#pragma unroll
    for (int o = 8; o; o >>= 1) qs += __shfl_xor_sync(0xffffffffu, qs, o);
    const float rs = rsqrtf(qs * (1.f / 64.f) + LN_EPS);

    float4 y;
    float g0 = gamma[q * 4 + 0], g1 = gamma[q * 4 + 1], g2 = gamma[q * 4 + 2], g3 = gamma[q * 4 + 3];
    float b0 = beta[q * 4 + 0],  b1 = beta[q * 4 + 1],  b2 = beta[q * 4 + 2],  b3 = beta[q * 4 + 3];
    float t0 = d0 * rs * g0 + b0;
    float t1 = d1 * rs * g1 + b1;
    float t2 = d2 * rs * g2 + b2;
    float t3 = d3 * rs * g3 + b3;
    y.x = t0 / (1.f + __expf(-t0));
    y.y = t1 / (1.f + __expf(-t1));
    y.z = t2 / (1.f + __expf(-t2));
    y.w = t3 / (1.f + __expf(-t3));
    ((float4*)(zout + (size_t)n * HID))[q] = y;
}

// ---------------- launcher ----------------
extern "C" void kernel_launch(void* const* d_in, const int* in_sizes, int n_in,
                              void* d_out, int out_size) {
    (void)in_sizes; (void)n_in; (void)out_size;
    const float* h     = (const float*)d_in[1];
    const void*  ei    = d_in[2];
    const float* ea    = (const float*)d_in[3];
    const float* W     = (const float*)d_in[4];
    const float* We    = (const float*)d_in[5];
    const float* as_   = (const float*)d_in[6];
    const float* ad_   = (const float*)d_in[7];
    const float* ae_   = (const float*)d_in[8];
    const float* bias  = (const float*)d_in[9];
    const float* gamma = (const float*)d_in[10];
    const float* beta  = (const float*)d_in[11];
    float* out = (float*)d_out;

    const int smem_bytes = 17024 * 4;   // 68096 B
    cudaFuncSetAttribute(k_node_proj, cudaFuncAttributeMaxDynamicSharedMemorySize, smem_bytes);

    float* zbuf = nullptr;
    cudaGetSymbolAddress((void**)&zbuf, g_z);

    // ---- preamble: CSR build (edge_index / edge_attr are layer-invariant) ----
    k_detect_zero<<<(N_NODES + 255) / 256, 256>>>((const int*)ei);
    k_convert<<<(N_EDGES + 255) / 256, 256>>>(ei);
    k_scanA<<<N_SCAN_BLOCKS, SCAN_BLK>>>();
    k_scanB<<<1, 64>>>();
    k_scanC<<<N_SCAN_BLOCKS, SCAN_BLK>>>();
    k_fill<<<(N_EDGES + 255) / 256, 256>>>(ea);

    const float* zin = h;
    for (int l = 0; l < L_LAYERS; l++) {
        k_M<<<1, 32>>>(We + (size_t)l * 3 * HC, ae_ + (size_t)l * HC);
        k_node_proj<<<444, 256, smem_bytes>>>(zin, W + (size_t)l * HID * HC,
                                              as_ + (size_t)l * HC, ad_ + (size_t)l * HC);
        k_gat_msg<<<N_NODES / 16, 256>>>(l == 0 ? zbuf : out,
                                         bias + (size_t)l * HID,
                                         gamma + (size_t)l * HID,
                                         beta + (size_t)l * HID);
        zin = zbuf;
    }
}

// round 9
// speedup vs baseline: 2.2733x; 1.0797x over previous
#include <cuda_runtime.h>
#include <cuda_fp16.h>
#include <cstdint>

#define N_NODES 50000
#define N_EDGES 800000
#define HID 64
#define HEADS 4
#define CDIM 64
#define HC 256   // HEADS*CDIM
#define L_LAYERS 2
#define NEG_SLOPE 0.2f
#define LN_EPS 1e-5f
#define SCAN_BLK 1024
#define N_SCAN_BLOCKS ((N_NODES + SCAN_BLK - 1) / SCAN_BLK)   // 49

// ---------------- device scratch (no allocations allowed) ----------------
__device__ __half g_xh[(size_t)N_NODES * HC];     // projected nodes, fp16 [N,256]
__device__ float g_as[N_NODES * HEADS];           // alpha_src [N,4]
__device__ float g_ad[N_NODES * HEADS];           // alpha_dst [N,4]
__device__ float g_exs[(size_t)N_EDGES * HEADS];  // exp(alpha), CSR order [E,4]
__device__ float g_ea_csr[(size_t)N_EDGES * 4];   // edge_attr in CSR order [E,4]
__device__ float g_z[(size_t)N_NODES * HID];      // inter-layer activations
__device__ int   g_src[N_EDGES];
__device__ int   g_dst[N_EDGES];
__device__ int   g_csr_src[N_EDGES];              // src id per CSR slot
__device__ int   g_rowptr[N_NODES + 1];
__device__ int   g_cur[N_NODES];
__device__ int   g_deg[N_NODES];
__device__ int   g_bsum[N_SCAN_BLOCKS];
__device__ int   g_boff[N_SCAN_BLOCKS];
__device__ float g_M2[2 * 12];                    // edge-attr dual matrices, both layers
__device__ int   g_is64;

// ---------------- K0a: detect dtype + zero degrees (fused) ----------------
__global__ void k_detect_zero(const int* __restrict__ ei32) {
    const int i = blockIdx.x * blockDim.x + threadIdx.x;
    if (i < N_NODES) g_deg[i] = 0;
    if (i == 0) {
        int zeros = 0;
        for (int k = 1; k < 256; k += 2) if (ei32[k] == 0) zeros++;
        g_is64 = (zeros > 100) ? 1 : 0;   // int64 data: high words all zero
    }
}

// ---------------- K0b: normalize edge index + count degrees ----------------
__global__ void k_convert(const void* __restrict__ ei) {
    const int e = blockIdx.x * blockDim.x + threadIdx.x;
    if (e >= N_EDGES) return;
    int s, d;
    if (g_is64) {
        const long long* p = (const long long*)ei;
        s = (int)p[e]; d = (int)p[N_EDGES + e];
    } else {
        const int* p = (const int*)ei;
        s = p[e]; d = p[N_EDGES + e];
    }
    g_src[e] = s;
    g_dst[e] = d;
    atomicAdd(&g_deg[d], 1);
}

// ---------------- K0c: scan phase A — per-block exclusive scan ----------------
__global__ void __launch_bounds__(SCAN_BLK) k_scanA() {
    __shared__ int warp_sums[32];
    const int tid = threadIdx.x;
    const int i = blockIdx.x * SCAN_BLK + tid;
    const int v = (i < N_NODES) ? g_deg[i] : 0;
    int x = v;
#pragma unroll
    for (int o = 1; o < 32; o <<= 1) {
        int y = __shfl_up_sync(0xffffffffu, x, o);
        if ((tid & 31) >= o) x += y;
    }
    if ((tid & 31) == 31) warp_sums[tid >> 5] = x;
    __syncthreads();
    if (tid < 32) {
        int w = warp_sums[tid];
#pragma unroll
        for (int o = 1; o < 32; o <<= 1) {
            int y = __shfl_up_sync(0xffffffffu, w, o);
            if (tid >= o) w += y;
        }
        warp_sums[tid] = w;
    }
    __syncthreads();
    const int excl = x - v + ((tid >= 32) ? warp_sums[(tid >> 5) - 1] : 0);
    if (i < N_NODES) g_rowptr[i] = excl;
    if (tid == SCAN_BLK - 1) g_bsum[blockIdx.x] = excl + v;
}

// ---------------- K0d: scan phase B — scan the 49 block sums ----------------
__global__ void k_scanB() {
    __shared__ int s0;
    const int tid = threadIdx.x;   // 64 threads
    const int v = (tid < N_SCAN_BLOCKS) ? g_bsum[tid] : 0;
    int x = v;
#pragma unroll
    for (int o = 1; o < 32; o <<= 1) {
        int y = __shfl_up_sync(0xffffffffu, x, o);
        if ((tid & 31) >= o) x += y;
    }
    if (tid == 31) s0 = x;
    __syncthreads();
    if (tid >= 32) x += s0;
    if (tid < N_SCAN_BLOCKS) g_boff[tid] = x - v;
    if (tid == N_SCAN_BLOCKS - 1) g_rowptr[N_NODES] = x;
}

// ---------------- K0e: scan phase C — add block offsets ----------------
__global__ void __launch_bounds__(SCAN_BLK) k_scanC() {
    const int i = blockIdx.x * SCAN_BLK + threadIdx.x;
    if (i < N_NODES) {
        const int r = g_rowptr[i] + g_boff[blockIdx.x];
        g_rowptr[i] = r;
        g_cur[i] = r;
    }
}

// ---------------- K0f: fill CSR (src id + edge_attr gathered to CSR order) ----------------
__global__ void k_fill(const float* __restrict__ ea) {
    const int e = blockIdx.x * blockDim.x + threadIdx.x;
    if (e >= N_EDGES) return;
    const int d = g_dst[e];
    const int pos = atomicAdd(&g_cur[d], 1);
    g_csr_src[pos] = g_src[e];
    const float* p = ea + (size_t)e * 3;
    ((float4*)g_ea_csr)[pos] = make_float4(p[0], p[1], p[2], 0.f);
}

// ---------------- K0g: M[l][d][h] for BOTH layers in one launch ----------------
__global__ void k_M_both(const float* __restrict__ We, const float* __restrict__ a_e) {
    const int t = threadIdx.x;
    if (t < 24) {
        const int l = t / 12, r = t % 12;
        const int d = r >> 2, h = r & 3;
        const float* Wel = We + (size_t)l * 3 * HC;
        const float* ael = a_e + (size_t)l * HC;
        float s = 0.f;
        for (int c = 0; c < CDIM; c++)
            s += Wel[d * HC + h * CDIM + c] * ael[h * CDIM + c];
        g_M2[t] = s;   // layout g_M2[l*12 + d*4 + h]
    }
}

// ---------------- K1: node projection (fp16 out) + alpha_src/alpha_dst ----------------
#define NB 8
__global__ void __launch_bounds__(256) k_node_proj(
    const float* __restrict__ z, const float* __restrict__ W,
    const float* __restrict__ a_s, const float* __restrict__ a_d)
{
    extern __shared__ float smem[];
    float* Wsh  = smem;                 // 64*256 = 16384 floats
    float* zshT = smem + 16384;         // [k][nb] transposed, 512 floats
    float* reds = smem + 16896;         // 64 floats
    float* redd = smem + 16960;         // 64 floats

    const int tid = threadIdx.x;
    for (int i = tid; i < (HID * HC) / 4; i += 256)
        ((float4*)Wsh)[i] = ((const float4*)W)[i];
    const float as = a_s[tid];
    const float ad = a_d[tid];
    __syncthreads();

    const int lane = tid & 31;
    const int wid = tid >> 5;
    const int nblocks = gridDim.x;

    for (int g = blockIdx.x; g * NB < N_NODES; g += nblocks) {
        const int n0 = g * NB;
        for (int i = tid; i < NB * HID; i += 256) {
            const int nb = i >> 6, k = i & 63;
            zshT[k * NB + nb] = z[(size_t)n0 * HID + i];
        }
        __syncthreads();

        float acc[NB];
#pragma unroll
        for (int nb = 0; nb < NB; nb++) acc[nb] = 0.f;

#pragma unroll
        for (int k = 0; k < HID; k++) {
            const float w = Wsh[k * HC + tid];
            const float4 za = ((float4*)zshT)[k * 2];
            const float4 zb = ((float4*)zshT)[k * 2 + 1];
            acc[0] = fmaf(za.x, w, acc[0]);
            acc[1] = fmaf(za.y, w, acc[1]);
            acc[2] = fmaf(za.z, w, acc[2]);
            acc[3] = fmaf(za.w, w, acc[3]);
            acc[4] = fmaf(zb.x, w, acc[4]);
            acc[5] = fmaf(zb.y, w, acc[5]);
            acc[6] = fmaf(zb.z, w, acc[6]);
            acc[7] = fmaf(zb.w, w, acc[7]);
        }

#pragma unroll
        for (int nb = 0; nb < NB; nb++)
            g_xh[(size_t)(n0 + nb) * HC + tid] = __float2half(acc[nb]);

        // alpha reductions use the fp32 accumulators (no fp16 error here)
#pragma unroll
        for (int nb = 0; nb < NB; nb++) {
            float ps = acc[nb] * as;
            float pd = acc[nb] * ad;
#pragma unroll
            for (int o = 16; o; o >>= 1) {
                ps += __shfl_down_sync(0xffffffffu, ps, o);
                pd += __shfl_down_sync(0xffffffffu, pd, o);
            }
            if (lane == 0) { reds[nb * 8 + wid] = ps; redd[nb * 8 + wid] = pd; }
        }
        __syncthreads();
        if (tid < 32) {
            const int nb = tid >> 2, h = tid & 3;
            g_as[(n0 + nb) * HEADS + h] = reds[nb * 8 + 2 * h] + reds[nb * 8 + 2 * h + 1];
            g_ad[(n0 + nb) * HEADS + h] = redd[nb * 8 + 2 * h] + redd[nb * 8 + 2 * h + 1];
        }
        __syncthreads();
    }
}

// ---------------- K2: fused alpha + CSR message pass + finalize ----------------
// 16 threads per dst node. fp16 x: lane q loads heads{0,1} and heads{2,3}
// slices (16B each) of its 8 channels; shfl_xor(8) combines head-halves.
__global__ void __launch_bounds__(256) k_gat_msg(
    int layer, float* __restrict__ zout, const float* __restrict__ bias,
    const float* __restrict__ gamma, const float* __restrict__ beta)
{
    const int t = threadIdx.x;
    const int q = t & 15;
    const int n = blockIdx.x * 16 + (t >> 4);
    const int row0 = g_rowptr[n];
    const int row1 = g_rowptr[n + 1];

    const float* M = g_M2 + layer * 12;
    const float4 ad4 = *(const float4*)(g_ad + n * 4);
    const float M0 = M[0], M1 = M[1], M2_ = M[2],  M3  = M[3];
    const float M4 = M[4], M5 = M[5], M6  = M[6],  M7  = M[7];
    const float M8 = M[8], M9 = M[9], M10 = M[10], M11 = M[11];

    // sweep 1: alpha -> exp per edge (lane-strided), denom accumulation,
    // coalesced store of ex into CSR order.
    float4 dn = make_float4(0.f, 0.f, 0.f, 0.f);
    for (int j = row0 + q; j < row1; j += 16) {
        const int s = g_csr_src[j];
        const float4 as4 = *(const float4*)(g_as + s * 4);
        const float4 ea4 = ((const float4*)g_ea_csr)[j];
        float a0 = as4.x + ad4.x + ea4.x * M0  + ea4.y * M4 + ea4.z * M8;
        float a1 = as4.y + ad4.y + ea4.x * M1  + ea4.y * M5 + ea4.z * M9;
        float a2 = as4.z + ad4.z + ea4.x * M2_ + ea4.y * M6 + ea4.z * M10;
        float a3 = as4.w + ad4.w + ea4.x * M3  + ea4.y * M7 + ea4.z * M11;
        a0 = (a0 < 0.f) ? NEG_SLOPE * a0 : a0;
        a1 = (a1 < 0.f) ? NEG_SLOPE * a1 : a1;
        a2 = (a2 < 0.f) ? NEG_SLOPE * a2 : a2;
        a3 = (a3 < 0.f) ? NEG_SLOPE * a3 : a3;
        // softmax shift-invariance + alpha ~ O(10): segment-max pass skipped.
        const float4 ex = make_float4(__expf(a0), __expf(a1), __expf(a2), __expf(a3));
        ((float4*)g_exs)[j] = ex;
        dn.x += ex.x; dn.y += ex.y; dn.z += ex.z; dn.w += ex.w;
    }
#pragma unroll
    for (int o = 8; o; o >>= 1) {
        dn.x += __shfl_xor_sync(0xffffffffu, dn.x, o);
        dn.y += __shfl_xor_sync(0xffffffffu, dn.y, o);
        dn.z += __shfl_xor_sync(0xffffffffu, dn.z, o);
        dn.w += __shfl_xor_sync(0xffffffffu, dn.w, o);
    }
    const float i0 = __frcp_rn(dn.x + 1e-16f);
    const float i1 = __frcp_rn(dn.y + 1e-16f);
    const float i2 = __frcp_rn(dn.z + 1e-16f);
    const float i3 = __frcp_rn(dn.w + 1e-16f);
    __syncwarp();   // order g_exs stores before cross-lane readback

    // sweep 2: serial edge walk; lane q owns channels 8*(q&7)..+7.
    // Load A covers head (q<8 ? 0 : 1), load B covers head (q<8 ? 2 : 3).
    float accA[8], accB[8];
#pragma unroll
    for (int i = 0; i < 8; i++) { accA[i] = 0.f; accB[i] = 0.f; }

    for (int j = row0; j < row1; j++) {
        const int s = g_csr_src[j];
        const float4 ex = ((const float4*)g_exs)[j];
        const float cA = (q < 8) ? (ex.x * i0) : (ex.y * i1);
        const float cB = (q < 8) ? (ex.z * i2) : (ex.w * i3);
        const __half* xr = g_xh + (size_t)s * HC;
        const uint4 hA = *(const uint4*)(xr + 8 * q);          // heads 0|1
        const uint4 hB = *(const uint4*)(xr + 128 + 8 * q);    // heads 2|3
        const float2 a0 = __half22float2(*(const __half2*)&hA.x);
        const float2 a1 = __half22float2(*(const __half2*)&hA.y);
        const float2 a2 = __half22float2(*(const __half2*)&hA.z);
        const float2 a3 = __half22float2(*(const __half2*)&hA.w);
        const float2 b0 = __half22float2(*(const __half2*)&hB.x);
        const float2 b1 = __half22float2(*(const __half2*)&hB.y);
        const float2 b2 = __half22float2(*(const __half2*)&hB.z);
        const float2 b3 = __half22float2(*(const __half2*)&hB.w);
        accA[0] = fmaf(cA, a0.x, accA[0]); accA[1] = fmaf(cA, a0.y, accA[1]);
        accA[2] = fmaf(cA, a1.x, accA[2]); accA[3] = fmaf(cA, a1.y, accA[3]);
        accA[4] = fmaf(cA, a2.x, accA[4]); accA[5] = fmaf(cA, a2.y, accA[5]);
        accA[6] = fmaf(cA, a3.x, accA[6]); accA[7] = fmaf(cA, a3.y, accA[7]);
        accB[0] = fmaf(cB, b0.x, accB[0]); accB[1] = fmaf(cB, b0.y, accB[1]);
        accB[2] = fmaf(cB, b1.x, accB[2]); accB[3] = fmaf(cB, b1.y, accB[3]);
        accB[4] = fmaf(cB, b2.x, accB[4]); accB[5] = fmaf(cB, b2.y, accB[5]);
        accB[6] = fmaf(cB, b3.x, accB[6]); accB[7] = fmaf(cB, b3.y, accB[7]);
    }

    // combine the two head-halves across the 8-lane pairs
    float tot[8];
#pragma unroll
    for (int i = 0; i < 8; i++) {
        float v = accA[i] + accB[i];
        v += __shfl_xor_sync(0xffffffffu, v, 8);
        tot[i] = v;   // lane q now has full sum over 4 heads for c=8*(q&7)+i
    }

    // finalize: head-mean + bias + LN + SiLU (values mirrored in lane pairs)
    const int c0i = 8 * (q & 7);
    float v[8];
    float s = 0.f;
#pragma unroll
    for (int i = 0; i < 8; i++) {
        v[i] = 0.25f * tot[i] + bias[c0i + i];
        s += v[i];
    }
#pragma unroll
    for (int o = 4; o; o >>= 1) s += __shfl_xor_sync(0xffffffffu, s, o);
    const float mu = s * (1.f / 64.f);
    float qs = 0.f;
#pragma unroll
    for (int i = 0; i < 8; i++) {
        v[i] -= mu;
        qs += v[i] * v[i];
    }
#pragma unroll
    for (int o = 4; o; o >>= 1) qs += __shfl_xor_sync(0xffffffffu, qs, o);
    const float rs = rsqrtf(qs * (1.f / 64.f) + LN_EPS);

    if (q < 8) {
        float y[8];
#pragma unroll
        for (int i = 0; i < 8; i++) {
            const float tv = v[i] * rs * gamma[c0i + i] + beta[c0i + i];
            y[i] = tv / (1.f + __expf(-tv));
        }
        float4* dst = (float4*)(zout + (size_t)n * HID + c0i);
        dst[0] = make_float4(y[0], y[1], y[2], y[3]);
        dst[1] = make_float4(y[4], y[5], y[6], y[7]);
    }
}

// ---------------- launcher ----------------
extern "C" void kernel_launch(void* const* d_in, const int* in_sizes, int n_in,
                              void* d_out, int out_size) {
    (void)in_sizes; (void)n_in; (void)out_size;
    const float* h     = (const float*)d_in[1];
    const void*  ei    = d_in[2];
    const float* ea    = (const float*)d_in[3];
    const float* W     = (const float*)d_in[4];
    const float* We    = (const float*)d_in[5];
    const float* as_   = (const float*)d_in[6];
    const float* ad_   = (const float*)d_in[7];
    const float* ae_   = (const float*)d_in[8];
    const float* bias  = (const float*)d_in[9];
    const float* gamma = (const float*)d_in[10];
    const float* beta  = (const float*)d_in[11];
    float* out = (float*)d_out;

    const int smem_bytes = 17024 * 4;   // 68096 B
    cudaFuncSetAttribute(k_node_proj, cudaFuncAttributeMaxDynamicSharedMemorySize, smem_bytes);

    float* zbuf = nullptr;
    cudaGetSymbolAddress((void**)&zbuf, g_z);

    // ---- preamble: CSR build + both layers' M (all layer-invariant) ----
    k_detect_zero<<<(N_NODES + 255) / 256, 256>>>((const int*)ei);
    k_convert<<<(N_EDGES + 255) / 256, 256>>>(ei);
    k_scanA<<<N_SCAN_BLOCKS, SCAN_BLK>>>();
    k_scanB<<<1, 64>>>();
    k_scanC<<<N_SCAN_BLOCKS, SCAN_BLK>>>();
    k_fill<<<(N_EDGES + 255) / 256, 256>>>(ea);
    k_M_both<<<1, 32>>>(We, ae_);

    const float* zin = h;
    for (int l = 0; l < L_LAYERS; l++) {
        k_node_proj<<<444, 256, smem_bytes>>>(zin, W + (size_t)l * HID * HC,
                                              as_ + (size_t)l * HC, ad_ + (size_t)l * HC);
        k_gat_msg<<<N_NODES / 16, 256>>>(l, l == 0 ? zbuf : out,
                                         bias + (size_t)l * HID,
                                         gamma + (size_t)l * HID,
                                         beta + (size_t)l * HID);
        zin = zbuf;
    }
}